// round 9
// baseline (speedup 1.0000x reference)
#include <cuda_runtime.h>
#include <cuda_fp16.h>

// AdderNet 2D (K=3,S=1,P=1): out[n,f,y,x] = -sum_{c,i,j} |W[f,c,i,j] - xpad[n,c,y+i,x+j]|
// x: [8,64,32,32] f32, W: [64,64,3,3] f32, out: [8,64,32,32] f32.
//
// 1024 CTAs (2 channel-halves x 4 fg x 16 row-tiles(RT=2) x 8 n), 256 thr,
// launch_bounds(256,5) -> 10 warps/SMSP, ~1% wave quantization.
// fp16 HADD2 core (abs folded), promote fp16->fp32 every 4 channels.
// Channel halves combined with atomicAdd (REDG) after zero-init kernel.

#define CIN   64
#define NFILT 64
#define HW    32
#define NIMG  8

#define FG    16
#define RT    2
#define XROWS (RT + 2)          // 4
#define XCOLS 34
#define CH    32                // channels per CTA (one half)

#define SX_ELEMS (CH * XROWS * XCOLS)    // 4352 halves = 8704 B
#define SW_ELEMS (CH * 9 * FG)           // 4608 halves = 9216 B
#define SMEM_BYTES (SX_ELEMS * 2 + SW_ELEMS * 2)   // 17920 B ; sR (12KB) aliases sX

#define OUT_ELEMS (NIMG * NFILT * HW * HW)          // 524288

__global__ __launch_bounds__(256, 8)
void zero_kernel(float* __restrict__ out)
{
    int i = (blockIdx.x * 256 + threadIdx.x) * 4;
    float4 z = {0.f, 0.f, 0.f, 0.f};
    *(float4*)(out + i) = z;
}

__global__ __launch_bounds__(256, 5)
void adder2d_kernel(const float* __restrict__ x,
                    const float* __restrict__ W,
                    float* __restrict__ out)
{
    extern __shared__ __half smemh[];
    __half* sX = smemh;                    // [c 0..31][r 0..3][col 0..33], zero pad
    __half* sW = smemh + SX_ELEMS;         // [k=c*9+tap][ff 0..15], NEGATED
    float*  sR = (float*)smemh;            // aliases after main loop: [3][16][64]

    const int tid = threadIdx.x;           // 0..255
    const int sub = tid >> 6;              // 0..3 channel subgroup (8 ch each)
    const int wk  = tid & 63;              // worker = one output position
    const int yw  = wk >> 5;               // 0..1
    const int col = wk & 31;
    const int bx  = blockIdx.x;            // 0..7 : fg(2b) | chhalf(1b)
    const int fg  = bx >> 1;
    const int chh = bx & 1;
    const int rt  = blockIdx.y;            // 0..15
    const int n   = blockIdx.z;            // 0..7
    const int y0    = rt * RT;
    const int f0    = fg * FG;
    const int cbase = chh * CH;

    // ---- load padded x slab (32 channels), fp32 -> fp16 ----
    const float* xn = x + ((size_t)n * CIN + cbase) * (HW * HW);
    for (int idx = tid; idx < SX_ELEMS; idx += 256) {
        int c   = idx / (XROWS * XCOLS);
        int rem = idx - c * (XROWS * XCOLS);
        int r   = rem / XCOLS;
        int cc  = rem - r * XCOLS;
        int gr  = y0 - 1 + r;
        int gc  = cc - 1;
        float v = 0.0f;
        if ((unsigned)gr < HW && (unsigned)gc < HW)
            v = xn[(c * HW + gr) * HW + gc];
        sX[idx] = __float2half_rn(v);
    }
    // ---- NEGATED fp16 weights: sW[k*16 + ff] = -W[(f0+ff)*576 + cbase*9 + k] ----
    for (int idx = tid; idx < SW_ELEMS; idx += 256) {
        int ff = idx / (CH * 9);
        int k  = idx - ff * (CH * 9);
        sW[k * FG + ff] = __float2half_rn(-W[(f0 + ff) * (CIN * 9) + cbase * 9 + k]);
    }
    __syncthreads();

    float facc[16];
#pragma unroll
    for (int p = 0; p < 16; p++) facc[p] = 0.0f;

    const __half* xrow = sX + (sub * 8) * (XROWS * XCOLS) + yw * XCOLS + col;
    const __half* wch  = sW + (sub * 8) * 9 * FG;

#pragma unroll 1
    for (int g = 0; g < 2; g++) {          // 2 groups x 4 channels
        __half2 hacc[8];
#pragma unroll
        for (int t = 0; t < 8; t++) hacc[t] = __float2half2_rn(0.0f);

#pragma unroll
        for (int cc = 0; cc < 4; cc++) {   // 4 channels per promote (36 taps)
#pragma unroll
            for (int i = 0; i < 3; i++) {
                __half2 xa[3];
#pragma unroll
                for (int j = 0; j < 3; j++)
                    xa[j] = __half2half2(xrow[i * XCOLS + j]);
#pragma unroll
                for (int j = 0; j < 3; j++) {
                    const uint4 rA = *(const uint4*)(wch + (i * 3 + j) * FG);     // f 0..7
                    const uint4 rB = *(const uint4*)(wch + (i * 3 + j) * FG + 8); // f 8..15
                    const __half2* wa = (const __half2*)&rA;
                    const __half2* wb = (const __half2*)&rB;
#pragma unroll
                    for (int q = 0; q < 4; q++) {
                        __half2 d;
                        d = __hadd2(xa[j], wa[q]); hacc[q]     = __hadd2(hacc[q],     __habs2(d));
                        d = __hadd2(xa[j], wb[q]); hacc[4 + q] = __hadd2(hacc[4 + q], __habs2(d));
                    }
                }
            }
            xrow += XROWS * XCOLS;
            wch  += 9 * FG;
        }
#pragma unroll
        for (int t = 0; t < 8; t++) {
            float2 f = __half22float2(hacc[t]);
            facc[2 * t]     += f.x;
            facc[2 * t + 1] += f.y;
        }
    }

    // ---- combine 4 subgroups (sR aliases sX) ----
    __syncthreads();
    if (sub != 0) {
        float* buf = sR + (size_t)(sub - 1) * (16 * 64);
#pragma unroll
        for (int p = 0; p < 16; p++) buf[p * 64 + wk] = facc[p];   // conflict-free
    }
    __syncthreads();

    if (sub == 0) {
#pragma unroll
        for (int p = 0; p < 16; p++) {
            float s = facc[p];
#pragma unroll
            for (int r = 0; r < 3; r++)
                s += sR[(size_t)r * (16 * 64) + p * 64 + wk];
            facc[p] = s;
        }
        // ---- REDG combine across channel halves: t = g*4+q ; f = g*8+2q+lane ----
        const int gy = y0 + yw;
#pragma unroll
        for (int t = 0; t < 8; t++) {
            int g = t >> 2;
            int q = t & 3;
            int f = g * 8 + q * 2;
            float* outp = out + (((size_t)n * NFILT + f0 + f) * HW + gy) * HW + col;
            atomicAdd(outp,           -facc[2 * t]);
            atomicAdd(outp + HW * HW, -facc[2 * t + 1]);
        }
    }
}

extern "C" void kernel_launch(void* const* d_in, const int* in_sizes, int n_in,
                              void* d_out, int out_size)
{
    const float* x = (const float*)d_in[0];
    const float* W = (const float*)d_in[1];
    if (n_in >= 2 && in_sizes[0] == NFILT * CIN * 9 && in_sizes[1] == NIMG * CIN * HW * HW) {
        const float* t = x; x = W; W = t;
    }
    float* out = (float*)d_out;

    zero_kernel<<<OUT_ELEMS / (256 * 4), 256>>>(out);

    dim3 grid(8, HW / RT, NIMG);            // 8 x 16 x 8 = 1024 CTAs
    adder2d_kernel<<<grid, 256, SMEM_BYTES>>>(x, W, out);
}

// round 10
// speedup vs baseline: 1.1797x; 1.1797x over previous
#include <cuda_runtime.h>
#include <cuda_fp16.h>

// AdderNet 2D (K=3,S=1,P=1): out[n,f,y,x] = -sum_{c,i,j} |W[f,c,i,j] - xpad[n,c,y+i,x+j]|
// x: [8,64,32,32] f32, W: [64,64,3,3] f32, out: [8,64,32,32] f32.
//
// R7 config (best: 256 CTAs, RT=4, 512 thr, 2 CTAs/SM, fp16 HADD2 core,
// promote fp16->fp32 every 2 channels) + ONE change: per tap, emit 8
// independent diffs THEN 8 accumulates (dep distance 8 instrs) so each warp
// sustains back-to-back fma-pipe issues instead of stalling on d->acc.

#define CIN   64
#define NFILT 64
#define HW    32
#define NIMG  8

#define FG    16
#define RT    4
#define XROWS (RT + 2)          // 6
#define XCOLS 34

#define SX_ELEMS (CIN * XROWS * XCOLS)   // 13056 halves = 26112 B
#define SW_ELEMS (CIN * 9 * FG)          // 9216 halves  = 18432 B
#define SMEM_BYTES ((SX_ELEMS + SW_ELEMS) * 2)   // 44544 B ; sR (24KB) aliases sX

__global__ __launch_bounds__(512, 2)
void adder2d_kernel(const float* __restrict__ x,
                    const float* __restrict__ W,
                    float* __restrict__ out)
{
    extern __shared__ __half smemh[];
    __half* sX = smemh;                       // [c][r 0..5][col 0..33] fp16, zero pad
    __half* sW = smemh + SX_ELEMS;            // [k=c*9+tap][ff 0..15]  fp16, NEGATED
    float*  sR = (float*)smemh;               // aliases after main loop: [3][16][128]

    const int tid = threadIdx.x;
    const int qtr = tid >> 7;                 // channel quarter 0..3
    const int wk  = tid & 127;                // worker = one output position
    const int yw  = wk >> 5;                  // 0..3
    const int col = wk & 31;
    const int fg  = blockIdx.x;               // 0..3
    const int rt  = blockIdx.y;               // 0..7
    const int n   = blockIdx.z;               // 0..7
    const int y0  = rt * RT;
    const int f0  = fg * FG;

    // ---- load padded x slab, fp32 -> fp16 ----
    const float* xn = x + (size_t)n * (CIN * HW * HW);
    for (int idx = tid; idx < SX_ELEMS; idx += 512) {
        int c   = idx / (XROWS * XCOLS);
        int rem = idx - c * (XROWS * XCOLS);
        int r   = rem / XCOLS;
        int cc  = rem - r * XCOLS;
        int gr  = y0 - 1 + r;
        int gc  = cc - 1;
        float v = 0.0f;
        if ((unsigned)gr < HW && (unsigned)gc < HW)
            v = xn[(c * HW + gr) * HW + gc];
        sX[idx] = __float2half_rn(v);
    }
    // ---- NEGATED fp16 weights: sW[k*16 + ff] = -W[(f0+ff)*576 + k] ----
    for (int idx = tid; idx < SW_ELEMS; idx += 512) {
        int ff = idx / (CIN * 9);
        int k  = idx - ff * (CIN * 9);
        sW[k * FG + ff] = __float2half_rn(-W[(f0 + ff) * (CIN * 9) + k]);
    }
    __syncthreads();

    float facc[16];
#pragma unroll
    for (int p = 0; p < 16; p++) facc[p] = 0.0f;

    const int cbeg = qtr * (CIN / 4);
    const __half* xrow = sX + cbeg * (XROWS * XCOLS) + yw * XCOLS + col;
    const __half* wch  = sW + cbeg * 9 * FG;

#pragma unroll 1
    for (int cp = 0; cp < CIN / 8; cp++) {     // 8 pairs of channels
        __half2 hacc[8];
#pragma unroll
        for (int t = 0; t < 8; t++) hacc[t] = __float2half2_rn(0.0f);

#pragma unroll
        for (int cc = 0; cc < 2; cc++) {       // 2 channels per promote (18 taps)
#pragma unroll
            for (int i = 0; i < 3; i++) {
                __half2 xa[3];
#pragma unroll
                for (int j = 0; j < 3; j++)
                    xa[j] = __half2half2(xrow[i * XCOLS + j]);
#pragma unroll
                for (int j = 0; j < 3; j++) {
                    const uint4 rA = *(const uint4*)(wch + (i * 3 + j) * FG);     // f 0..7
                    const uint4 rB = *(const uint4*)(wch + (i * 3 + j) * FG + 8); // f 8..15
                    const __half2* wa = (const __half2*)&rA;
                    const __half2* wb = (const __half2*)&rB;
                    // ---- 8 independent diffs, THEN 8 accumulates ----
                    __half2 dd[8];
#pragma unroll
                    for (int q = 0; q < 4; q++) {
                        dd[q]     = __hadd2(xa[j], wa[q]);
                        dd[4 + q] = __hadd2(xa[j], wb[q]);
                    }
#pragma unroll
                    for (int t = 0; t < 8; t++)
                        hacc[t] = __hadd2(hacc[t], __habs2(dd[t]));
                }
            }
            xrow += XROWS * XCOLS;
            wch  += 9 * FG;
        }
        // ---- promote fp16 partials (18 taps) into fp32 ----
#pragma unroll
        for (int t = 0; t < 8; t++) {
            float2 f = __half22float2(hacc[t]);
            facc[2 * t]     += f.x;
            facc[2 * t + 1] += f.y;
        }
    }

    // ---- combine 4 channel quarters (sR aliases sX, now dead) ----
    __syncthreads();
    if (qtr != 0) {
        float* buf = sR + (size_t)(qtr - 1) * (16 * 128);
#pragma unroll
        for (int p = 0; p < 16; p++) buf[p * 128 + wk] = facc[p];  // conflict-free
    }
    __syncthreads();

    if (qtr == 0) {
#pragma unroll
        for (int p = 0; p < 16; p++) {
            float s = facc[p];
#pragma unroll
            for (int r = 0; r < 3; r++)
                s += sR[(size_t)r * (16 * 128) + p * 128 + wk];
            facc[p] = s;
        }
        // ---- write: t = g*4 + q ; filter = g*8 + 2q + lane ----
        const int gy = y0 + yw;
#pragma unroll
        for (int t = 0; t < 8; t++) {
            int g = t >> 2;
            int q = t & 3;
            int f = g * 8 + q * 2;
            float* outp = out + (((size_t)n * NFILT + f0 + f) * HW + gy) * HW + col;
            outp[0]       = -facc[2 * t];
            outp[HW * HW] = -facc[2 * t + 1];
        }
    }
}

extern "C" void kernel_launch(void* const* d_in, const int* in_sizes, int n_in,
                              void* d_out, int out_size)
{
    const float* x = (const float*)d_in[0];
    const float* W = (const float*)d_in[1];
    if (n_in >= 2 && in_sizes[0] == NFILT * CIN * 9 && in_sizes[1] == NIMG * CIN * HW * HW) {
        const float* t = x; x = W; W = t;
    }
    float* out = (float*)d_out;

    dim3 grid(NFILT / FG, HW / RT, NIMG);   // 4 x 8 x 8 = 256 CTAs, 2 per SM
    adder2d_kernel<<<grid, 512, SMEM_BYTES>>>(x, W, out);
}